// round 5
// baseline (speedup 1.0000x reference)
#include <cuda_runtime.h>
#include <math.h>

// ReciprocalRankLoss: B=256, P=4, N=1024, D=512, fp32.
// rank_p = #{negatives with sim > pos_p} + stable ties among positives;
// single streaming pass: 4 counters + sum(exp(sim/T)) per b.
//
// R5 == R4 resubmit (R4 hit a harness-side cudaErrorSystemNotReady before
// any kernel ran): 256-thread CTAs, grid=512 (one CTA per half-b), occ 4
// => 592 slots, SINGLE wave with 4-vs-3 slot balance (vs R3's 2-vs-1).
// Fused last-CTA finalize kept.

static constexpr int B_   = 256;
static constexpr int P_   = 4;
static constexpr int NNEG = 1024;
static constexpr int D_   = 512;
static constexpr int SPLIT = 2;
static constexpr int GRID  = B_ * SPLIT;             // 512
static constexpr int NW    = 8;                      // warps per CTA
static constexpr int ROWS_PER_CTA  = NNEG / SPLIT;   // 512
static constexpr int ROWS_PER_WARP = ROWS_PER_CTA / NW; // 64

__device__ float g_ps[B_][P_];
__device__ float g_zpart[GRID];
__device__ int   g_cnt[GRID][P_];
__device__ int   g_done = 0;

__global__ void __launch_bounds__(256, 4)
rrl_fused_kernel(const float* __restrict__ anchor,
                 const float* __restrict__ positives,
                 const float* __restrict__ negatives,
                 float* __restrict__ out)
{
    __shared__ float sa[D_];
    __shared__ float s_red[NW];
    __shared__ float s_sumexp[NW];
    __shared__ int   s_cnt[NW][P_];
    __shared__ float s_ps[P_];
    __shared__ float s_na;
    __shared__ int   s_islast;

    const int cta  = blockIdx.x;
    const int b    = cta >> 1;
    const int half = cta & 1;
    const int tid  = threadIdx.x;
    const int lane = tid & 31;
    const int wid  = tid >> 5;

    // ---- anchor row -> smem (2 elems/thread), block-reduce squared norm ----
    float av0 = anchor[(size_t)b * D_ + tid];
    float av1 = anchor[(size_t)b * D_ + tid + 256];
    sa[tid]       = av0;
    sa[tid + 256] = av1;
    float sq = av0 * av0 + av1 * av1;
    #pragma unroll
    for (int o = 16; o; o >>= 1) sq += __shfl_xor_sync(0xffffffffu, sq, o);
    if (lane == 0) s_red[wid] = sq;
    __syncthreads();
    if (tid < 32) {
        float v = (lane < NW) ? s_red[lane] : 0.0f;
        #pragma unroll
        for (int o = 4; o; o >>= 1) v += __shfl_xor_sync(0xffffffffu, v, o);
        if (lane == 0) s_na = sqrtf(v);
    }
    __syncthreads();
    const float na = s_na;

    const float4* sa4 = reinterpret_cast<const float4*>(sa);
    const float4 a0 = sa4[lane];
    const float4 a1 = sa4[lane + 32];
    const float4 a2 = sa4[lane + 64];
    const float4 a3 = sa4[lane + 96];

    // ---- positive sims: warps 0..3, one per positive ----
    if (wid < P_) {
        const float4* pr = reinterpret_cast<const float4*>(
            positives + ((size_t)b * P_ + wid) * D_);
        float4 v0 = pr[lane], v1 = pr[lane + 32], v2 = pr[lane + 64], v3 = pr[lane + 96];
        float dot = v0.x*a0.x + v0.y*a0.y + v0.z*a0.z + v0.w*a0.w
                  + v1.x*a1.x + v1.y*a1.y + v1.z*a1.z + v1.w*a1.w
                  + v2.x*a2.x + v2.y*a2.y + v2.z*a2.z + v2.w*a2.w
                  + v3.x*a3.x + v3.y*a3.y + v3.z*a3.z + v3.w*a3.w;
        float nr  = v0.x*v0.x + v0.y*v0.y + v0.z*v0.z + v0.w*v0.w
                  + v1.x*v1.x + v1.y*v1.y + v1.z*v1.z + v1.w*v1.w
                  + v2.x*v2.x + v2.y*v2.y + v2.z*v2.z + v2.w*v2.w
                  + v3.x*v3.x + v3.y*v3.y + v3.z*v3.z + v3.w*v3.w;
        #pragma unroll
        for (int o = 16; o; o >>= 1) {
            dot += __shfl_xor_sync(0xffffffffu, dot, o);
            nr  += __shfl_xor_sync(0xffffffffu, nr, o);
        }
        if (lane == 0) {
            float ps = dot / fmaxf(na * sqrtf(nr), 1e-8f);
            s_ps[wid] = ps;
            if (half == 0) g_ps[b][wid] = ps;
        }
    }
    __syncthreads();
    const float p0 = s_ps[0], p1 = s_ps[1], p2 = s_ps[2], p3 = s_ps[3];

    // ---- stream this half's 512 negative rows (64 per warp) ----
    float sumExp = 0.0f;
    int c0 = 0, c1 = 0, c2 = 0, c3 = 0;
    const int rbase = half * ROWS_PER_CTA + wid * ROWS_PER_WARP;
    #pragma unroll 2
    for (int r = 0; r < ROWS_PER_WARP; ++r) {
        const float4* nr4 = reinterpret_cast<const float4*>(
            negatives + ((size_t)b * NNEG + rbase + r) * D_);
        float4 v0 = nr4[lane], v1 = nr4[lane + 32], v2 = nr4[lane + 64], v3 = nr4[lane + 96];
        float dot = v0.x*a0.x + v0.y*a0.y + v0.z*a0.z + v0.w*a0.w
                  + v1.x*a1.x + v1.y*a1.y + v1.z*a1.z + v1.w*a1.w
                  + v2.x*a2.x + v2.y*a2.y + v2.z*a2.z + v2.w*a2.w
                  + v3.x*a3.x + v3.y*a3.y + v3.z*a3.z + v3.w*a3.w;
        float nrm = v0.x*v0.x + v0.y*v0.y + v0.z*v0.z + v0.w*v0.w
                  + v1.x*v1.x + v1.y*v1.y + v1.z*v1.z + v1.w*v1.w
                  + v2.x*v2.x + v2.y*v2.y + v2.z*v2.z + v2.w*v2.w
                  + v3.x*v3.x + v3.y*v3.y + v3.z*v3.z + v3.w*v3.w;
        #pragma unroll
        for (int o = 16; o; o >>= 1) {
            dot += __shfl_xor_sync(0xffffffffu, dot, o);
            nrm += __shfl_xor_sync(0xffffffffu, nrm, o);
        }
        float sim = dot / fmaxf(na * sqrtf(nrm), 1e-8f);
        if (lane == 0) {
            sumExp += expf(sim * 10.0f);   // 1/TEMPERATURE
            c0 += (sim > p0);
            c1 += (sim > p1);
            c2 += (sim > p2);
            c3 += (sim > p3);
        }
    }
    if (lane == 0) {
        s_sumexp[wid] = sumExp;
        s_cnt[wid][0] = c0; s_cnt[wid][1] = c1;
        s_cnt[wid][2] = c2; s_cnt[wid][3] = c3;
    }
    __syncthreads();

    // ---- per-CTA partials -> global (deterministic serial reduce over warps) ----
    if (tid == 0) {
        float Z = 0.0f;
        int cc0 = 0, cc1 = 0, cc2 = 0, cc3 = 0;
        #pragma unroll
        for (int w = 0; w < NW; ++w) {
            Z += s_sumexp[w];
            cc0 += s_cnt[w][0]; cc1 += s_cnt[w][1];
            cc2 += s_cnt[w][2]; cc3 += s_cnt[w][3];
        }
        g_zpart[cta] = Z;
        g_cnt[cta][0] = cc0; g_cnt[cta][1] = cc1;
        g_cnt[cta][2] = cc2; g_cnt[cta][3] = cc3;
        __threadfence();
        int ticket = atomicAdd(&g_done, 1);
        s_islast = (ticket == GRID - 1);
    }
    __syncthreads();
    if (!s_islast) return;

    // ---- last CTA: finalize all 256 batch rows (one per thread) ----
    __threadfence();
    float err = 0.0f, possum = 0.0f;
    {
        const int bb = tid;   // 256 threads, 256 rows
        float ps[P_];
        #pragma unroll
        for (int p = 0; p < P_; ++p) ps[p] = g_ps[bb][p];
        float ev[P_];
        #pragma unroll
        for (int p = 0; p < P_; ++p) ev[p] = expf(ps[p] * 10.0f);
        float Z = g_zpart[2 * bb] + g_zpart[2 * bb + 1]
                + ev[0] + ev[1] + ev[2] + ev[3];
        #pragma unroll
        for (int p = 0; p < P_; ++p) {
            int rank = g_cnt[2 * bb][p] + g_cnt[2 * bb + 1][p];
            #pragma unroll
            for (int q = 0; q < P_; ++q) {
                if (q == p) continue;
                // stable argsort of -probs among positives
                if (ps[q] > ps[p] || (q < p && ps[q] == ps[p])) rank++;
            }
            err += (ev[p] / Z) * (1.0f / (float)(rank + 1));
        }
        possum = ps[0] + ps[1] + ps[2] + ps[3];
    }
    #pragma unroll
    for (int o = 16; o; o >>= 1) {
        err    += __shfl_xor_sync(0xffffffffu, err, o);
        possum += __shfl_xor_sync(0xffffffffu, possum, o);
    }
    __shared__ float s_e[NW], s_s[NW];
    if (lane == 0) { s_e[wid] = err; s_s[wid] = possum; }
    __syncthreads();
    if (tid == 0) {
        float esum = 0.0f, ssum = 0.0f;
        #pragma unroll
        for (int w = 0; w < NW; ++w) { esum += s_e[w]; ssum += s_s[w]; }
        float mean_err = esum / (float)B_;
        float mean_pos = ssum / (float)(B_ * P_);
        out[0] = -mean_err + 0.3f * (1.0f - mean_pos);
        g_done = 0;   // reset ticket for next graph replay
    }
}

extern "C" void kernel_launch(void* const* d_in, const int* in_sizes, int n_in,
                              void* d_out, int out_size)
{
    const float* anchor    = (const float*)d_in[0];
    const float* positives = (const float*)d_in[1];
    const float* negatives = (const float*)d_in[2];
    float* out = (float*)d_out;

    rrl_fused_kernel<<<GRID, 256>>>(anchor, positives, negatives, out);
}

// round 6
// speedup vs baseline: 1.0116x; 1.0116x over previous
#include <cuda_runtime.h>
#include <math.h>

// ReciprocalRankLoss: B=256, P=4, N=1024, D=512, fp32.
// rank_p = #{negatives with sim > pos_p} + stable ties among positives;
// one streaming pass: 4 counters + sum(exp(sim/T)) per b.
//
// R6: R3 structure (grid=256, 512 thr, occ 2 — best measured: 88.1us,
// 6.17TB/s) + explicit software-pipelined row loads (prefetch row r+1
// before the shuffle-reduce of row r) so LDG issue never sits behind the
// 5-stage dependent SHFL chain. Fused last-CTA finalize kept.

static constexpr int B_   = 256;
static constexpr int P_   = 4;
static constexpr int NNEG = 1024;
static constexpr int D_   = 512;
static constexpr int NW   = 16;                      // warps per CTA
static constexpr int ROWS_PER_WARP = NNEG / NW;      // 64

__device__ float g_err[B_];
__device__ float g_possum[B_];
__device__ int   g_done = 0;

__global__ void __launch_bounds__(512, 2)
rrl_fused_kernel(const float* __restrict__ anchor,
                 const float* __restrict__ positives,
                 const float* __restrict__ negatives,
                 float* __restrict__ out)
{
    __shared__ float sa[D_];
    __shared__ float s_red[NW];
    __shared__ float s_sumexp[NW];
    __shared__ int   s_cnt[NW][P_];
    __shared__ float s_ps[P_];
    __shared__ float s_na;
    __shared__ int   s_islast;

    const int b    = blockIdx.x;
    const int tid  = threadIdx.x;
    const int lane = tid & 31;
    const int wid  = tid >> 5;

    // ---- anchor row -> smem, block-reduce squared norm ----
    float av = anchor[(size_t)b * D_ + tid];
    sa[tid] = av;
    float sq = av * av;
    #pragma unroll
    for (int o = 16; o; o >>= 1) sq += __shfl_xor_sync(0xffffffffu, sq, o);
    if (lane == 0) s_red[wid] = sq;
    __syncthreads();
    if (tid < 32) {
        float v = (lane < NW) ? s_red[lane] : 0.0f;
        #pragma unroll
        for (int o = 8; o; o >>= 1) v += __shfl_xor_sync(0xffffffffu, v, o);
        if (lane == 0) s_na = sqrtf(v);
    }
    __syncthreads();
    const float na = s_na;

    const float4* sa4 = reinterpret_cast<const float4*>(sa);
    const float4 a0 = sa4[lane];
    const float4 a1 = sa4[lane + 32];
    const float4 a2 = sa4[lane + 64];
    const float4 a3 = sa4[lane + 96];

    // ---- positive sims: one warp per positive ----
    if (wid < P_) {
        const float4* pr = reinterpret_cast<const float4*>(
            positives + ((size_t)b * P_ + wid) * D_);
        float4 v0 = pr[lane], v1 = pr[lane + 32], v2 = pr[lane + 64], v3 = pr[lane + 96];
        float dot = v0.x*a0.x + v0.y*a0.y + v0.z*a0.z + v0.w*a0.w
                  + v1.x*a1.x + v1.y*a1.y + v1.z*a1.z + v1.w*a1.w
                  + v2.x*a2.x + v2.y*a2.y + v2.z*a2.z + v2.w*a2.w
                  + v3.x*a3.x + v3.y*a3.y + v3.z*a3.z + v3.w*a3.w;
        float nr  = v0.x*v0.x + v0.y*v0.y + v0.z*v0.z + v0.w*v0.w
                  + v1.x*v1.x + v1.y*v1.y + v1.z*v1.z + v1.w*v1.w
                  + v2.x*v2.x + v2.y*v2.y + v2.z*v2.z + v2.w*v2.w
                  + v3.x*v3.x + v3.y*v3.y + v3.z*v3.z + v3.w*v3.w;
        #pragma unroll
        for (int o = 16; o; o >>= 1) {
            dot += __shfl_xor_sync(0xffffffffu, dot, o);
            nr  += __shfl_xor_sync(0xffffffffu, nr, o);
        }
        if (lane == 0) s_ps[wid] = dot / fmaxf(na * sqrtf(nr), 1e-8f);
    }
    __syncthreads();
    const float p0 = s_ps[0], p1 = s_ps[1], p2 = s_ps[2], p3 = s_ps[3];

    // ---- stream 64 negative rows per warp, software-pipelined ----
    float sumExp = 0.0f;
    int c0 = 0, c1 = 0, c2 = 0, c3 = 0;
    const float4* base4 = reinterpret_cast<const float4*>(
        negatives + ((size_t)b * NNEG + wid * ROWS_PER_WARP) * D_) + lane;
    // row stride in float4 units: D_/4 = 128
    float4 n0 = base4[0];
    float4 n1 = base4[32];
    float4 n2 = base4[64];
    float4 n3 = base4[96];
    #pragma unroll 2
    for (int r = 0; r < ROWS_PER_WARP; ++r) {
        const float4 v0 = n0, v1 = n1, v2 = n2, v3 = n3;
        if (r + 1 < ROWS_PER_WARP) {
            const float4* nxt = base4 + (size_t)(r + 1) * (D_ / 4);
            n0 = nxt[0];
            n1 = nxt[32];
            n2 = nxt[64];
            n3 = nxt[96];
        }
        float dot = v0.x*a0.x + v0.y*a0.y + v0.z*a0.z + v0.w*a0.w
                  + v1.x*a1.x + v1.y*a1.y + v1.z*a1.z + v1.w*a1.w
                  + v2.x*a2.x + v2.y*a2.y + v2.z*a2.z + v2.w*a2.w
                  + v3.x*a3.x + v3.y*a3.y + v3.z*a3.z + v3.w*a3.w;
        float nrm = v0.x*v0.x + v0.y*v0.y + v0.z*v0.z + v0.w*v0.w
                  + v1.x*v1.x + v1.y*v1.y + v1.z*v1.z + v1.w*v1.w
                  + v2.x*v2.x + v2.y*v2.y + v2.z*v2.z + v2.w*v2.w
                  + v3.x*v3.x + v3.y*v3.y + v3.z*v3.z + v3.w*v3.w;
        #pragma unroll
        for (int o = 16; o; o >>= 1) {
            dot += __shfl_xor_sync(0xffffffffu, dot, o);
            nrm += __shfl_xor_sync(0xffffffffu, nrm, o);
        }
        float sim = dot / fmaxf(na * sqrtf(nrm), 1e-8f);
        if (lane == 0) {
            sumExp += expf(sim * 10.0f);   // 1/TEMPERATURE
            c0 += (sim > p0);
            c1 += (sim > p1);
            c2 += (sim > p2);
            c3 += (sim > p3);
        }
    }
    if (lane == 0) {
        s_sumexp[wid] = sumExp;
        s_cnt[wid][0] = c0; s_cnt[wid][1] = c1;
        s_cnt[wid][2] = c2; s_cnt[wid][3] = c3;
    }
    __syncthreads();

    // ---- finalize this batch row (deterministic serial reduce over 16 warps) ----
    if (tid == 0) {
        float Z = 0.0f;
        int cc[P_] = {0, 0, 0, 0};
        #pragma unroll
        for (int w = 0; w < NW; ++w) {
            Z += s_sumexp[w];
            cc[0] += s_cnt[w][0]; cc[1] += s_cnt[w][1];
            cc[2] += s_cnt[w][2]; cc[3] += s_cnt[w][3];
        }
        float ps[P_] = {p0, p1, p2, p3};
        float ev[P_];
        #pragma unroll
        for (int p = 0; p < P_; ++p) ev[p] = expf(ps[p] * 10.0f);
        Z += ev[0] + ev[1] + ev[2] + ev[3];
        float err = 0.0f;
        #pragma unroll
        for (int p = 0; p < P_; ++p) {
            int rank = cc[p];
            #pragma unroll
            for (int q = 0; q < P_; ++q) {
                if (q == p) continue;
                // stable argsort of -probs among positives
                if (ps[q] > ps[p] || (q < p && ps[q] == ps[p])) rank++;
            }
            err += (ev[p] / Z) * (1.0f / (float)(rank + 1));
        }
        g_err[b]    = err;
        g_possum[b] = p0 + p1 + p2 + p3;
        __threadfence();
        int ticket = atomicAdd(&g_done, 1);
        s_islast = (ticket == B_ - 1);
    }
    __syncthreads();
    if (!s_islast) return;

    // ---- last CTA: reduce 256 per-b partials to the scalar ----
    __threadfence();
    float e = 0.0f, s = 0.0f;
    if (tid < B_) {
        e = g_err[tid];
        s = g_possum[tid];
    }
    #pragma unroll
    for (int o = 16; o; o >>= 1) {
        e += __shfl_xor_sync(0xffffffffu, e, o);
        s += __shfl_xor_sync(0xffffffffu, s, o);
    }
    __shared__ float s_e[NW], s_s[NW];
    if (lane == 0) { s_e[wid] = e; s_s[wid] = s; }
    __syncthreads();
    if (tid == 0) {
        float esum = 0.0f, ssum = 0.0f;
        #pragma unroll
        for (int w = 0; w < 8; ++w) { esum += s_e[w]; ssum += s_s[w]; }  // warps 8..15 contributed zeros
        float mean_err = esum / (float)B_;
        float mean_pos = ssum / (float)(B_ * P_);
        out[0] = -mean_err + 0.3f * (1.0f - mean_pos);
        g_done = 0;   // reset ticket for next graph replay
    }
}

extern "C" void kernel_launch(void* const* d_in, const int* in_sizes, int n_in,
                              void* d_out, int out_size)
{
    const float* anchor    = (const float*)d_in[0];
    const float* positives = (const float*)d_in[1];
    const float* negatives = (const float*)d_in[2];
    float* out = (float*)d_out;

    rrl_fused_kernel<<<B_, 512>>>(anchor, positives, negatives, out);
}

// round 7
// speedup vs baseline: 1.0202x; 1.0085x over previous
#include <cuda_runtime.h>
#include <math.h>

// ReciprocalRankLoss: B=256, P=4, N=1024, D=512, fp32.
// rank_p = #{negatives with sim > pos_p} + stable ties among positives;
// one streaming pass: 4 counters + sum(exp(sim/T)) per b.
//
// R7: R3 structure verbatim (grid=256, 512 thr, occ 2, plain float4 loads,
// unroll 2 — best measured 88.1us / 6.17TB/s). Only change: per-row
// sqrt/div/exp moved under lane==0 and lowered to rsqrtf + __expf
// (was executing on all 32 lanes per row). Fused last-CTA finalize kept.

static constexpr int B_   = 256;
static constexpr int P_   = 4;
static constexpr int NNEG = 1024;
static constexpr int D_   = 512;
static constexpr int NW   = 16;                      // warps per CTA
static constexpr int ROWS_PER_WARP = NNEG / NW;      // 64

__device__ float g_err[B_];
__device__ float g_possum[B_];
__device__ int   g_done = 0;

__global__ void __launch_bounds__(512, 2)
rrl_fused_kernel(const float* __restrict__ anchor,
                 const float* __restrict__ positives,
                 const float* __restrict__ negatives,
                 float* __restrict__ out)
{
    __shared__ float sa[D_];
    __shared__ float s_red[NW];
    __shared__ float s_sumexp[NW];
    __shared__ int   s_cnt[NW][P_];
    __shared__ float s_ps[P_];
    __shared__ float s_na;
    __shared__ int   s_islast;

    const int b    = blockIdx.x;
    const int tid  = threadIdx.x;
    const int lane = tid & 31;
    const int wid  = tid >> 5;

    // ---- anchor row -> smem, block-reduce squared norm ----
    float av = anchor[(size_t)b * D_ + tid];
    sa[tid] = av;
    float sq = av * av;
    #pragma unroll
    for (int o = 16; o; o >>= 1) sq += __shfl_xor_sync(0xffffffffu, sq, o);
    if (lane == 0) s_red[wid] = sq;
    __syncthreads();
    if (tid < 32) {
        float v = (lane < NW) ? s_red[lane] : 0.0f;
        #pragma unroll
        for (int o = 8; o; o >>= 1) v += __shfl_xor_sync(0xffffffffu, v, o);
        if (lane == 0) s_na = sqrtf(v);
    }
    __syncthreads();
    const float na     = s_na;
    const float inv_na = 1.0f / na;   // norms ~ sqrt(512); never degenerate

    const float4* sa4 = reinterpret_cast<const float4*>(sa);
    const float4 a0 = sa4[lane];
    const float4 a1 = sa4[lane + 32];
    const float4 a2 = sa4[lane + 64];
    const float4 a3 = sa4[lane + 96];

    // ---- positive sims: one warp per positive (exact formula incl. clamp) ----
    if (wid < P_) {
        const float4* pr = reinterpret_cast<const float4*>(
            positives + ((size_t)b * P_ + wid) * D_);
        float4 v0 = pr[lane], v1 = pr[lane + 32], v2 = pr[lane + 64], v3 = pr[lane + 96];
        float dot = v0.x*a0.x + v0.y*a0.y + v0.z*a0.z + v0.w*a0.w
                  + v1.x*a1.x + v1.y*a1.y + v1.z*a1.z + v1.w*a1.w
                  + v2.x*a2.x + v2.y*a2.y + v2.z*a2.z + v2.w*a2.w
                  + v3.x*a3.x + v3.y*a3.y + v3.z*a3.z + v3.w*a3.w;
        float nr  = v0.x*v0.x + v0.y*v0.y + v0.z*v0.z + v0.w*v0.w
                  + v1.x*v1.x + v1.y*v1.y + v1.z*v1.z + v1.w*v1.w
                  + v2.x*v2.x + v2.y*v2.y + v2.z*v2.z + v2.w*v2.w
                  + v3.x*v3.x + v3.y*v3.y + v3.z*v3.z + v3.w*v3.w;
        #pragma unroll
        for (int o = 16; o; o >>= 1) {
            dot += __shfl_xor_sync(0xffffffffu, dot, o);
            nr  += __shfl_xor_sync(0xffffffffu, nr, o);
        }
        if (lane == 0) s_ps[wid] = dot / fmaxf(na * sqrtf(nr), 1e-8f);
    }
    __syncthreads();
    const float p0 = s_ps[0], p1 = s_ps[1], p2 = s_ps[2], p3 = s_ps[3];

    // ---- stream 64 negative rows per warp ----
    float sumExp = 0.0f;
    int c0 = 0, c1 = 0, c2 = 0, c3 = 0;
    const int rbase = wid * ROWS_PER_WARP;
    #pragma unroll 2
    for (int r = 0; r < ROWS_PER_WARP; ++r) {
        const float4* nr4 = reinterpret_cast<const float4*>(
            negatives + ((size_t)b * NNEG + rbase + r) * D_);
        float4 v0 = nr4[lane], v1 = nr4[lane + 32], v2 = nr4[lane + 64], v3 = nr4[lane + 96];
        float dot = v0.x*a0.x + v0.y*a0.y + v0.z*a0.z + v0.w*a0.w
                  + v1.x*a1.x + v1.y*a1.y + v1.z*a1.z + v1.w*a1.w
                  + v2.x*a2.x + v2.y*a2.y + v2.z*a2.z + v2.w*a2.w
                  + v3.x*a3.x + v3.y*a3.y + v3.z*a3.z + v3.w*a3.w;
        float nrm = v0.x*v0.x + v0.y*v0.y + v0.z*v0.z + v0.w*v0.w
                  + v1.x*v1.x + v1.y*v1.y + v1.z*v1.z + v1.w*v1.w
                  + v2.x*v2.x + v2.y*v2.y + v2.z*v2.z + v2.w*v2.w
                  + v3.x*v3.x + v3.y*v3.y + v3.z*v3.z + v3.w*v3.w;
        #pragma unroll
        for (int o = 16; o; o >>= 1) {
            dot += __shfl_xor_sync(0xffffffffu, dot, o);
            nrm += __shfl_xor_sync(0xffffffffu, nrm, o);
        }
        if (lane == 0) {
            // sim = dot / (na * sqrt(nrm)); norms never near eps for this data
            float sim = dot * rsqrtf(nrm) * inv_na;
            sumExp += __expf(sim * 10.0f);   // 1/TEMPERATURE
            c0 += (sim > p0);
            c1 += (sim > p1);
            c2 += (sim > p2);
            c3 += (sim > p3);
        }
    }
    if (lane == 0) {
        s_sumexp[wid] = sumExp;
        s_cnt[wid][0] = c0; s_cnt[wid][1] = c1;
        s_cnt[wid][2] = c2; s_cnt[wid][3] = c3;
    }
    __syncthreads();

    // ---- finalize this batch row (deterministic serial reduce over 16 warps) ----
    if (tid == 0) {
        float Z = 0.0f;
        int cc[P_] = {0, 0, 0, 0};
        #pragma unroll
        for (int w = 0; w < NW; ++w) {
            Z += s_sumexp[w];
            cc[0] += s_cnt[w][0]; cc[1] += s_cnt[w][1];
            cc[2] += s_cnt[w][2]; cc[3] += s_cnt[w][3];
        }
        float ps[P_] = {p0, p1, p2, p3};
        float ev[P_];
        #pragma unroll
        for (int p = 0; p < P_; ++p) ev[p] = expf(ps[p] * 10.0f);
        Z += ev[0] + ev[1] + ev[2] + ev[3];
        float err = 0.0f;
        #pragma unroll
        for (int p = 0; p < P_; ++p) {
            int rank = cc[p];
            #pragma unroll
            for (int q = 0; q < P_; ++q) {
                if (q == p) continue;
                // stable argsort of -probs among positives
                if (ps[q] > ps[p] || (q < p && ps[q] == ps[p])) rank++;
            }
            err += (ev[p] / Z) * (1.0f / (float)(rank + 1));
        }
        g_err[b]    = err;
        g_possum[b] = p0 + p1 + p2 + p3;
        __threadfence();
        int ticket = atomicAdd(&g_done, 1);
        s_islast = (ticket == B_ - 1);
    }
    __syncthreads();
    if (!s_islast) return;

    // ---- last CTA: reduce 256 per-b partials to the scalar ----
    __threadfence();
    float e = 0.0f, s = 0.0f;
    if (tid < B_) {
        e = g_err[tid];
        s = g_possum[tid];
    }
    #pragma unroll
    for (int o = 16; o; o >>= 1) {
        e += __shfl_xor_sync(0xffffffffu, e, o);
        s += __shfl_xor_sync(0xffffffffu, s, o);
    }
    __shared__ float s_e[NW], s_s[NW];
    if (lane == 0) { s_e[wid] = e; s_s[wid] = s; }
    __syncthreads();
    if (tid == 0) {
        float esum = 0.0f, ssum = 0.0f;
        #pragma unroll
        for (int w = 0; w < 8; ++w) { esum += s_e[w]; ssum += s_s[w]; }  // warps 8..15 contributed zeros
        float mean_err = esum / (float)B_;
        float mean_pos = ssum / (float)(B_ * P_);
        out[0] = -mean_err + 0.3f * (1.0f - mean_pos);
        g_done = 0;   // reset ticket for next graph replay
    }
}

extern "C" void kernel_launch(void* const* d_in, const int* in_sizes, int n_in,
                              void* d_out, int out_size)
{
    const float* anchor    = (const float*)d_in[0];
    const float* positives = (const float*)d_in[1];
    const float* negatives = (const float*)d_in[2];
    float* out = (float*)d_out;

    rrl_fused_kernel<<<B_, 512>>>(anchor, positives, negatives, out);
}

// round 8
// speedup vs baseline: 1.0681x; 1.0469x over previous
#include <cuda_runtime.h>
#include <math.h>

// ReciprocalRankLoss: B=256, P=4, N=1024, D=512, fp32.
// rank_p = #{negatives with sim > pos_p} + stable ties among positives;
// one streaming pass: 4 counters + sum(exp(sim/T)) per b.
//
// R8: R7 base (87.5us kernel) + interleaved row assignment: warp w takes
// rows {w, w+16, w+32, ...} so the 16 warps of a CTA sweep one contiguous
// 32KB window together (1 sequential 2MB stream per CTA) instead of 16
// private 128KB streams. Pure index change; everything else identical.

static constexpr int B_   = 256;
static constexpr int P_   = 4;
static constexpr int NNEG = 1024;
static constexpr int D_   = 512;
static constexpr int NW   = 16;                      // warps per CTA
static constexpr int ROWS_PER_WARP = NNEG / NW;      // 64

__device__ float g_err[B_];
__device__ float g_possum[B_];
__device__ int   g_done = 0;

__global__ void __launch_bounds__(512, 2)
rrl_fused_kernel(const float* __restrict__ anchor,
                 const float* __restrict__ positives,
                 const float* __restrict__ negatives,
                 float* __restrict__ out)
{
    __shared__ float sa[D_];
    __shared__ float s_red[NW];
    __shared__ float s_sumexp[NW];
    __shared__ int   s_cnt[NW][P_];
    __shared__ float s_ps[P_];
    __shared__ float s_na;
    __shared__ int   s_islast;

    const int b    = blockIdx.x;
    const int tid  = threadIdx.x;
    const int lane = tid & 31;
    const int wid  = tid >> 5;

    // ---- anchor row -> smem, block-reduce squared norm ----
    float av = anchor[(size_t)b * D_ + tid];
    sa[tid] = av;
    float sq = av * av;
    #pragma unroll
    for (int o = 16; o; o >>= 1) sq += __shfl_xor_sync(0xffffffffu, sq, o);
    if (lane == 0) s_red[wid] = sq;
    __syncthreads();
    if (tid < 32) {
        float v = (lane < NW) ? s_red[lane] : 0.0f;
        #pragma unroll
        for (int o = 8; o; o >>= 1) v += __shfl_xor_sync(0xffffffffu, v, o);
        if (lane == 0) s_na = sqrtf(v);
    }
    __syncthreads();
    const float na     = s_na;
    const float inv_na = 1.0f / na;   // norms ~ sqrt(512); never degenerate

    const float4* sa4 = reinterpret_cast<const float4*>(sa);
    const float4 a0 = sa4[lane];
    const float4 a1 = sa4[lane + 32];
    const float4 a2 = sa4[lane + 64];
    const float4 a3 = sa4[lane + 96];

    // ---- positive sims: one warp per positive (exact formula incl. clamp) ----
    if (wid < P_) {
        const float4* pr = reinterpret_cast<const float4*>(
            positives + ((size_t)b * P_ + wid) * D_);
        float4 v0 = pr[lane], v1 = pr[lane + 32], v2 = pr[lane + 64], v3 = pr[lane + 96];
        float dot = v0.x*a0.x + v0.y*a0.y + v0.z*a0.z + v0.w*a0.w
                  + v1.x*a1.x + v1.y*a1.y + v1.z*a1.z + v1.w*a1.w
                  + v2.x*a2.x + v2.y*a2.y + v2.z*a2.z + v2.w*a2.w
                  + v3.x*a3.x + v3.y*a3.y + v3.z*a3.z + v3.w*a3.w;
        float nr  = v0.x*v0.x + v0.y*v0.y + v0.z*v0.z + v0.w*v0.w
                  + v1.x*v1.x + v1.y*v1.y + v1.z*v1.z + v1.w*v1.w
                  + v2.x*v2.x + v2.y*v2.y + v2.z*v2.z + v2.w*v2.w
                  + v3.x*v3.x + v3.y*v3.y + v3.z*v3.z + v3.w*v3.w;
        #pragma unroll
        for (int o = 16; o; o >>= 1) {
            dot += __shfl_xor_sync(0xffffffffu, dot, o);
            nr  += __shfl_xor_sync(0xffffffffu, nr, o);
        }
        if (lane == 0) s_ps[wid] = dot / fmaxf(na * sqrtf(nr), 1e-8f);
    }
    __syncthreads();
    const float p0 = s_ps[0], p1 = s_ps[1], p2 = s_ps[2], p3 = s_ps[3];

    // ---- stream 64 negative rows per warp, rows interleaved across warps ----
    float sumExp = 0.0f;
    int c0 = 0, c1 = 0, c2 = 0, c3 = 0;
    #pragma unroll 2
    for (int r = 0; r < ROWS_PER_WARP; ++r) {
        const int row = wid + r * NW;   // warps sweep one 32KB window together
        const float4* nr4 = reinterpret_cast<const float4*>(
            negatives + ((size_t)b * NNEG + row) * D_);
        float4 v0 = nr4[lane], v1 = nr4[lane + 32], v2 = nr4[lane + 64], v3 = nr4[lane + 96];
        float dot = v0.x*a0.x + v0.y*a0.y + v0.z*a0.z + v0.w*a0.w
                  + v1.x*a1.x + v1.y*a1.y + v1.z*a1.z + v1.w*a1.w
                  + v2.x*a2.x + v2.y*a2.y + v2.z*a2.z + v2.w*a2.w
                  + v3.x*a3.x + v3.y*a3.y + v3.z*a3.z + v3.w*a3.w;
        float nrm = v0.x*v0.x + v0.y*v0.y + v0.z*v0.z + v0.w*v0.w
                  + v1.x*v1.x + v1.y*v1.y + v1.z*v1.z + v1.w*v1.w
                  + v2.x*v2.x + v2.y*v2.y + v2.z*v2.z + v2.w*v2.w
                  + v3.x*v3.x + v3.y*v3.y + v3.z*v3.z + v3.w*v3.w;
        #pragma unroll
        for (int o = 16; o; o >>= 1) {
            dot += __shfl_xor_sync(0xffffffffu, dot, o);
            nrm += __shfl_xor_sync(0xffffffffu, nrm, o);
        }
        if (lane == 0) {
            // sim = dot / (na * sqrt(nrm)); norms never near eps for this data
            float sim = dot * rsqrtf(nrm) * inv_na;
            sumExp += __expf(sim * 10.0f);   // 1/TEMPERATURE
            c0 += (sim > p0);
            c1 += (sim > p1);
            c2 += (sim > p2);
            c3 += (sim > p3);
        }
    }
    if (lane == 0) {
        s_sumexp[wid] = sumExp;
        s_cnt[wid][0] = c0; s_cnt[wid][1] = c1;
        s_cnt[wid][2] = c2; s_cnt[wid][3] = c3;
    }
    __syncthreads();

    // ---- finalize this batch row (deterministic serial reduce over 16 warps) ----
    if (tid == 0) {
        float Z = 0.0f;
        int cc[P_] = {0, 0, 0, 0};
        #pragma unroll
        for (int w = 0; w < NW; ++w) {
            Z += s_sumexp[w];
            cc[0] += s_cnt[w][0]; cc[1] += s_cnt[w][1];
            cc[2] += s_cnt[w][2]; cc[3] += s_cnt[w][3];
        }
        float ps[P_] = {p0, p1, p2, p3};
        float ev[P_];
        #pragma unroll
        for (int p = 0; p < P_; ++p) ev[p] = expf(ps[p] * 10.0f);
        Z += ev[0] + ev[1] + ev[2] + ev[3];
        float err = 0.0f;
        #pragma unroll
        for (int p = 0; p < P_; ++p) {
            int rank = cc[p];
            #pragma unroll
            for (int q = 0; q < P_; ++q) {
                if (q == p) continue;
                // stable argsort of -probs among positives
                if (ps[q] > ps[p] || (q < p && ps[q] == ps[p])) rank++;
            }
            err += (ev[p] / Z) * (1.0f / (float)(rank + 1));
        }
        g_err[b]    = err;
        g_possum[b] = p0 + p1 + p2 + p3;
        __threadfence();
        int ticket = atomicAdd(&g_done, 1);
        s_islast = (ticket == B_ - 1);
    }
    __syncthreads();
    if (!s_islast) return;

    // ---- last CTA: reduce 256 per-b partials to the scalar ----
    __threadfence();
    float e = 0.0f, s = 0.0f;
    if (tid < B_) {
        e = g_err[tid];
        s = g_possum[tid];
    }
    #pragma unroll
    for (int o = 16; o; o >>= 1) {
        e += __shfl_xor_sync(0xffffffffu, e, o);
        s += __shfl_xor_sync(0xffffffffu, s, o);
    }
    __shared__ float s_e[NW], s_s[NW];
    if (lane == 0) { s_e[wid] = e; s_s[wid] = s; }
    __syncthreads();
    if (tid == 0) {
        float esum = 0.0f, ssum = 0.0f;
        #pragma unroll
        for (int w = 0; w < 8; ++w) { esum += s_e[w]; ssum += s_s[w]; }  // warps 8..15 contributed zeros
        float mean_err = esum / (float)B_;
        float mean_pos = ssum / (float)(B_ * P_);
        out[0] = -mean_err + 0.3f * (1.0f - mean_pos);
        g_done = 0;   // reset ticket for next graph replay
    }
}

extern "C" void kernel_launch(void* const* d_in, const int* in_sizes, int n_in,
                              void* d_out, int out_size)
{
    const float* anchor    = (const float*)d_in[0];
    const float* positives = (const float*)d_in[1];
    const float* negatives = (const float*)d_in[2];
    float* out = (float*)d_out;

    rrl_fused_kernel<<<B_, 512>>>(anchor, positives, negatives, out);
}